// round 9
// baseline (speedup 1.0000x reference)
#include <cuda_runtime.h>

// LocalSpatialEncoding: enc=[rel(3),|rel|] -> (W1,BN,ReLU)[4] -> (W2,BN,ReLU)[8]
// B=8,N=16384,K=16. Output (B,N,K,8) fp32.
// R9: R8 + float4-granularity transpose staging with stride-5 swizzle:
//     4x STS.128 + 4x LDS.128 (both minimal 4-phase), replacing
//     8x STS.64 + 16x scalar LDS. Weights stay as 15 broadcast LDS.128.

#define LSE_EPS 1e-5f
#define TOTAL   (8 * 16384 * 16)   // 2097152 points
#define THREADS 256
#define WARPS   8
#define PTW     64                 // points per warp (32 lanes * 2)
#define SLOTS   160                // staging float4 slots per warp (5*31+3 = 158 used)

__device__ __forceinline__ float sqrt_ap(float x) {
    float r; asm("sqrt.approx.f32 %0,%1;" : "=f"(r) : "f"(x)); return r;
}

__global__ void __launch_bounds__(THREADS)
lse_main(const float* __restrict__ coords,
         const float* __restrict__ nbr,
         const float* __restrict__ W1, const float* __restrict__ g1,
         const float* __restrict__ b1, const float* __restrict__ m1,
         const float* __restrict__ v1,
         const float* __restrict__ W2, const float* __restrict__ g2,
         const float* __restrict__ b2, const float* __restrict__ m2,
         const float* __restrict__ v2,
         float* __restrict__ out)
{
    // Folded weights, float4-addressable:
    //   w4[0..3]  = W1' rows     w4[4]     = t1
    //   w4[5..12] = W2' rows     w4[13,14] = t2
    __shared__ __align__(16) float  sw[60];
    __shared__ __align__(16) float4 sbuf[WARPS][SLOTS];

    int t = threadIdx.x;
    if (t < 16) {
        int o = t >> 2;
        float s = g1[o] * rsqrtf(v1[o] + LSE_EPS);
        sw[t] = W1[t] * s;
        if ((t & 3) == 0) sw[16 + o] = b1[o] - m1[o] * s;
    } else if (t < 48) {
        int i = t - 16;
        int o = i >> 2;
        float s = g2[o] * rsqrtf(v2[o] + LSE_EPS);
        sw[20 + i] = W2[i] * s;
        if ((i & 3) == 0) sw[52 + o] = b2[o] - m2[o] * s;
    }
    __syncthreads();
    const float4* w4 = reinterpret_cast<const float4*>(sw);

    int g    = blockIdx.x * THREADS + t;   // thread owns points 2g, 2g+1
    int warp = t >> 5;
    int lane = t & 31;

    // ---- Loads: 6 neighbor floats = 3 x LDG.64 contiguous; center broadcast (8 thr) ----
    const float2* nb2 = reinterpret_cast<const float2*>(nbr) + (size_t)g * 3;
    float2 va = __ldg(nb2 + 0);
    float2 vb = __ldg(nb2 + 1);
    float2 vc = __ldg(nb2 + 2);

    const float* cp = coords + (size_t)(g >> 3) * 3;
    float c0 = __ldg(cp + 0), c1 = __ldg(cp + 1), c2 = __ldg(cp + 2);

    // pt0 = (va.x, va.y, vb.x), pt1 = (vb.y, vc.x, vc.y)
    float ax = va.x - c0, ay = va.y - c1, az = vb.x - c2;
    float bx = vb.y - c0, by = vc.x - c1, bz = vc.y - c2;
    float da = sqrt_ap(fmaf(ax, ax, fmaf(ay, ay, az * az)));
    float db = sqrt_ap(fmaf(bx, bx, fmaf(by, by, bz * bz)));

    // ---- Layer 1: one LDS.128 per output row, serves both points ----
    float4 t1v = w4[4];
    const float* t1p = reinterpret_cast<const float*>(&t1v);
    float ha[4], hb[4];
#pragma unroll
    for (int o = 0; o < 4; o++) {
        float4 w = w4[o];
        float acc = t1p[o];
        ha[o] = fmaxf(fmaf(ax, w.x, fmaf(ay, w.y, fmaf(az, w.z, fmaf(da, w.w, acc)))), 0.0f);
        hb[o] = fmaxf(fmaf(bx, w.x, fmaf(by, w.y, fmaf(bz, w.z, fmaf(db, w.w, acc)))), 0.0f);
    }

    // ---- Layer 2: one LDS.128 per output row ----
    float4 t2a = w4[13], t2b = w4[14];
    const float* t2p0 = reinterpret_cast<const float*>(&t2a);
    const float* t2p1 = reinterpret_cast<const float*>(&t2b);
    float ya[8], yb[8];
#pragma unroll
    for (int o = 0; o < 8; o++) {
        float4 w = w4[5 + o];
        float bias = (o < 4) ? t2p0[o] : t2p1[o - 4];
        ya[o] = fmaxf(fmaf(ha[0], w.x, fmaf(ha[1], w.y, fmaf(ha[2], w.z, fmaf(ha[3], w.w, bias)))), 0.0f);
        yb[o] = fmaxf(fmaf(hb[0], w.x, fmaf(hb[1], w.y, fmaf(hb[2], w.z, fmaf(hb[3], w.w, bias)))), 0.0f);
    }

    // ---- Stage to smem in point-major layout, stride-5-float4 swizzle ----
    // Thread's 4 float4s correspond to warp-region f4 indices f = 4*lane + j:
    //   j=0: pt0 ch0-3   j=1: pt0 ch4-7   j=2: pt1 ch0-3   j=3: pt1 ch4-7
    // Staged at slot 5*lane + j. STS.128 start banks 4*((5L+j)%8): 4 phases (minimal).
    {
        int sb = 5 * lane;
        sbuf[warp][sb + 0] = make_float4(ya[0], ya[1], ya[2], ya[3]);
        sbuf[warp][sb + 1] = make_float4(ya[4], ya[5], ya[6], ya[7]);
        sbuf[warp][sb + 2] = make_float4(yb[0], yb[1], yb[2], yb[3]);
        sbuf[warp][sb + 3] = make_float4(yb[4], yb[5], yb[6], yb[7]);
    }
    __syncwarp();

    // ---- Readback LDS.128 (4 phases, minimal) + coalesced STG.128 ----
    // Iter k: lane L handles f = L + 32k  ->  slot 5*(f>>2) + (f&3) = rb + 40k.
    int rb = 5 * (lane >> 2) + (lane & 3);
    int warpbase = blockIdx.x * (THREADS * 2) + warp * PTW;
    float4* o4 = reinterpret_cast<float4*>(out) + (size_t)warpbase * 2 + lane;
#pragma unroll
    for (int k = 0; k < 4; k++) {
        o4[32 * k] = sbuf[warp][rb + 40 * k];   // 32 lanes -> 512B contiguous per STG.128
    }
}

extern "C" void kernel_launch(void* const* d_in, const int* in_sizes, int n_in,
                              void* d_out, int out_size)
{
    const float* coords = (const float*)d_in[0];
    const float* nbr    = (const float*)d_in[1];
    const float* W1     = (const float*)d_in[2];
    const float* g1     = (const float*)d_in[3];
    const float* b1     = (const float*)d_in[4];
    const float* m1     = (const float*)d_in[5];
    const float* v1     = (const float*)d_in[6];
    const float* W2     = (const float*)d_in[7];
    const float* g2     = (const float*)d_in[8];
    const float* b2     = (const float*)d_in[9];
    const float* m2     = (const float*)d_in[10];
    const float* v2     = (const float*)d_in[11];
    float* out = (float*)d_out;

    int blocks = TOTAL / (THREADS * 2);   // 4096
    lse_main<<<blocks, THREADS>>>(coords, nbr, W1, g1, b1, m1, v1,
                                  W2, g2, b2, m2, v2, out);
}